// round 4
// baseline (speedup 1.0000x reference)
#include <cuda_runtime.h>

// YOLOv2 region loss — 4 cells/thread for ILP (issue/latency-bound per ncu R2/R3).
// B=16, A=5, C=80, H=W=64, N_GT=50, STRIDE=16, THRESH=0.6

#define NA 5
#define NC 80
#define NGT 50
#define HW 4096
#define CH 85
#define CPT 4
#define BLK 128
#define NBLOCKS 640      // 327680 cells / (128*4)

__device__ double g_part[NBLOCKS];
__device__ unsigned int g_flag;   // zero-init; last block resets each launch

__global__ __launch_bounds__(BLK) void rl_loss_kernel(
    const float* __restrict__ outp,
    const float* __restrict__ target,
    const float* __restrict__ anchors,
    float* __restrict__ out)
{
    __shared__ float4 s_box[NGT];      // x1,y1,x2,y2
    __shared__ float  s_m3sa[NGT];     // -3 * gt_area
    __shared__ float4 s_gt[NGT];       // cx,cy,w,h
    __shared__ float  s_cls[NGT];
    __shared__ double s_red[4];
    __shared__ int    s_last;

    const int cell0 = blockIdx.x * (BLK * CPT) + threadIdx.x;   // +128*c for c in 0..3
    const int ba    = cell0 >> 12;              // same for all 4 cells (512 | 4096)
    const int b     = ba / NA;
    const int a     = ba - b * NA;
    const int hw0   = cell0 & (HW - 1);

    if (threadIdx.x < NGT) {
        const float* t = target + ((size_t)b * NGT + threadIdx.x) * 5;
        float cls = t[0], cx = t[1], cy = t[2], gw = t[3], gh = t[4];
        float x1 = cx - gw * 0.5f, y1 = cy - gh * 0.5f;
        float x2 = cx + gw * 0.5f, y2 = cy + gh * 0.5f;
        s_box[threadIdx.x]  = make_float4(x1, y1, x2, y2);
        s_m3sa[threadIdx.x] = -3.0f * ((x2 - x1) * (y2 - y1));
        s_gt[threadIdx.x]   = make_float4(cx, cy, gw, gh);
        s_cls[threadIdx.x]  = cls;
    }
    __syncthreads();

    const float aw = anchors[2 * a];
    const float ah = anchors[2 * a + 1];
    // channel c of cell: ((b*A+a)*85 + ch)*4096 + hw
    const float* base = outp + ((size_t)ba * CH) * HW + hw0;

    float px1[CPT], py1[CPT], px2[CPT], py2[CPT];
    float cpa[CPT], conf[CPT], mk[CPT];

    #pragma unroll
    for (int c = 0; c < CPT; c++) {
        const float* bc = base + BLK * c;
        float t0 = bc[0];
        float t1 = bc[HW];
        float t2 = bc[2 * HW];
        float t3 = bc[3 * HW];
        conf[c]  = bc[4 * HW];
        int hwc = hw0 + BLK * c;
        int h = hwc >> 6, w = hwc & 63;
        float sx = __fdividef(1.0f, 1.0f + __expf(-t0));
        float sy = __fdividef(1.0f, 1.0f + __expf(-t1));
        float px = (sx + (float)w) * 16.0f;
        float py = (sy + (float)h) * 16.0f;
        float pw = __expf(t2) * aw;
        float ph = __expf(t3) * ah;
        px1[c] = px - pw * 0.5f;  py1[c] = py - ph * 0.5f;
        px2[c] = px + pw * 0.5f;  py2[c] = py + ph * 0.5f;
        float pa = (px2[c] - px1[c]) * (py2[c] - py1[c]);
        cpa[c] = -3.0f * (pa + 1e-6f);
        mk[c]  = -1e30f;
    }

    // ---- Phase 1: "any GT passes 0.6" — iou_n>0.6 <=> 8*I_n - 3*S_n > 0.
    // 4 independent streams hide LDS/FMNMX latency.
#pragma unroll 5
    for (int n = 0; n < NGT; n++) {
        float4 bx = s_box[n];
        float m3  = s_m3sa[n];
        #pragma unroll
        for (int c = 0; c < CPT; c++) {
            float cw = fminf(bx.z, px2[c]) - fmaxf(bx.x, px1[c]);
            float chh = fminf(bx.w, py2[c]) - fmaxf(bx.y, py1[c]);
            float I  = fmaxf(cw, 0.0f) * fmaxf(chh, 0.0f);
            mk[c] = fmaxf(mk[c], fmaf(I, 8.0f, m3 + cpa[c]));
        }
    }

    float loss = 0.0f;
    #pragma unroll
    for (int c = 0; c < CPT; c++) {
        if (mk[c] > 0.0f) {
            // ---- Phase 2 (rare): exact cross-multiplied argmax over I/S
            // (monotone-equivalent to iou; strict > keeps first index).
            float paeps = cpa[c] * (-1.0f / 3.0f);   // pred_area + eps
            float bI = -1.0f, bS = 1.0f;
            int bidx = 0;
            for (int n = 0; n < NGT; n++) {
                float4 bx = s_box[n];
                float cw = fminf(bx.z, px2[c]) - fmaxf(bx.x, px1[c]);
                float chh = fminf(bx.w, py2[c]) - fmaxf(bx.y, py1[c]);
                float I  = fmaxf(cw, 0.0f) * fmaxf(chh, 0.0f);
                float S  = s_m3sa[n] * (-1.0f / 3.0f) + paeps;
                if (I * bS > bI * S) { bI = I; bS = S; bidx = n; }
            }

            const float* bc = base + BLK * c;       // reload raw logits (L2-hot)
            float t0 = bc[0];
            float t1 = bc[HW];
            float t2 = bc[2 * HW];
            float t3 = bc[3 * HW];
            float4 g = s_gt[bidx];
            float d0 = t0 - g.x;
            float d1 = t1 - g.y;
            float d2 = t2 - g.z;
            float d3 = t3 - g.w;
            float dc = 5.0f * conf[c] - 5.0f;
            loss += d0 * d0 + d1 * d1 + d2 * d2 + d3 * d3 + dc * dc;

            // class NLL (logits ~N(0,1): unshifted logsumexp is safe)
            int idx = (int)s_cls[bidx];
            const float* cl = bc + (size_t)5 * HW;
            float ssum = 0.0f;
            for (int cc = 0; cc < NC; cc++)
                ssum += __expf(cl[(size_t)cc * HW]);
            loss += __logf(ssum) - cl[(size_t)idx * HW];
        } else {
            loss += conf[c] * conf[c];
        }
    }

    // block reduction in double
    double v = (double)loss;
    #pragma unroll
    for (int off = 16; off; off >>= 1)
        v += __shfl_down_sync(0xffffffffu, v, off);

    const int lane = threadIdx.x & 31;
    const int wid  = threadIdx.x >> 5;
    if (lane == 0) s_red[wid] = v;
    __syncthreads();
    if (threadIdx.x < 32) {
        v = (lane < 4) ? s_red[lane] : 0.0;
        v += __shfl_down_sync(0xffffffffu, v, 2);
        v += __shfl_down_sync(0xffffffffu, v, 1);
    }

    // last-block-reduces (single launch, graph-replay safe)
    if (threadIdx.x == 0) {
        g_part[blockIdx.x] = v;
        __threadfence();
        unsigned int done = atomicAdd(&g_flag, 1u);
        s_last = (done == NBLOCKS - 1);
    }
    __syncthreads();

    if (s_last) {
        double t = 0.0;
        for (int i = threadIdx.x; i < NBLOCKS; i += BLK)
            t += g_part[i];
        #pragma unroll
        for (int off = 16; off; off >>= 1)
            t += __shfl_down_sync(0xffffffffu, t, off);
        if (lane == 0) s_red[wid] = t;
        __syncthreads();
        if (threadIdx.x == 0) {
            double tot = s_red[0] + s_red[1] + s_red[2] + s_red[3];
            out[0] = (float)tot;
            atomicExch(&g_flag, 0u);
        }
    }
}

extern "C" void kernel_launch(void* const* d_in, const int* in_sizes, int n_in,
                              void* d_out, int out_size)
{
    const float* outp    = (const float*)d_in[0];
    const float* target  = (const float*)d_in[1];
    const float* anchors = (const float*)d_in[2];
    float* out = (float*)d_out;

    rl_loss_kernel<<<NBLOCKS, BLK>>>(outp, target, anchors, out);
}

// round 5
// speedup vs baseline: 1.1794x; 1.1794x over previous
#include <cuda_runtime.h>

// YOLOv2 region loss — 2 cells/thread (ILP at ~54% occupancy) + warp-cooperative
// class-NLL for the rare masked cells (kills the 80-deep serial LDG/MUFU chain).
// B=16, A=5, C=80, H=W=64, N_GT=50, STRIDE=16, THRESH=0.6

#define NA 5
#define NC 80
#define NGT 50
#define HW 4096
#define CH 85
#define CPT 2
#define BLK 256
#define NBLOCKS 640      // 327680 / (256*2)
#define FULL 0xffffffffu

__device__ double g_part[NBLOCKS];
__device__ unsigned int g_flag;   // zero-init; last block resets each launch

__global__ __launch_bounds__(BLK) void rl_loss_kernel(
    const float* __restrict__ outp,
    const float* __restrict__ target,
    const float* __restrict__ anchors,
    float* __restrict__ out)
{
    __shared__ float4 s_box[NGT];      // x1,y1,x2,y2
    __shared__ float  s_m3sa[NGT];     // -3 * gt_area
    __shared__ float4 s_gt[NGT];       // cx,cy,w,h
    __shared__ float  s_cls[NGT];
    __shared__ double s_red[8];
    __shared__ int    s_last;

    const int tid   = threadIdx.x;
    const int lane  = tid & 31;
    const int wid   = tid >> 5;
    const int cell0 = blockIdx.x * (BLK * CPT) + tid;   // second cell: +256
    const int ba    = cell0 >> 12;              // same for both cells (512 | 4096)
    const int b     = ba / NA;
    const int a     = ba - b * NA;
    const int hw0   = cell0 & (HW - 1);

    if (tid < NGT) {
        const float* t = target + ((size_t)b * NGT + tid) * 5;
        float cls = t[0], cx = t[1], cy = t[2], gw = t[3], gh = t[4];
        float x1 = cx - gw * 0.5f, y1 = cy - gh * 0.5f;
        float x2 = cx + gw * 0.5f, y2 = cy + gh * 0.5f;
        s_box[tid]  = make_float4(x1, y1, x2, y2);
        s_m3sa[tid] = -3.0f * ((x2 - x1) * (y2 - y1));
        s_gt[tid]   = make_float4(cx, cy, gw, gh);
        s_cls[tid]  = cls;
    }
    __syncthreads();

    const float aw = anchors[2 * a];
    const float ah = anchors[2 * a + 1];
    const float* base = outp + ((size_t)ba * CH) * HW + hw0;   // + c*HW per channel

    float px1[CPT], py1[CPT], px2[CPT], py2[CPT];
    float c3pe[CPT], conf[CPT], mk[CPT];

    #pragma unroll
    for (int c = 0; c < CPT; c++) {
        const float* bc = base + BLK * c;
        float t0 = bc[0];
        float t1 = bc[HW];
        float t2 = bc[2 * HW];
        float t3 = bc[3 * HW];
        conf[c]  = bc[4 * HW];
        int hwc = hw0 + BLK * c;
        int h = hwc >> 6, w = hwc & 63;
        float sx = __fdividef(1.0f, 1.0f + __expf(-t0));
        float sy = __fdividef(1.0f, 1.0f + __expf(-t1));
        float px = (sx + (float)w) * 16.0f;
        float py = (sy + (float)h) * 16.0f;
        float pw = __expf(t2) * aw;
        float ph = __expf(t3) * ah;
        px1[c] = px - pw * 0.5f;  py1[c] = py - ph * 0.5f;
        px2[c] = px + pw * 0.5f;  py2[c] = py + ph * 0.5f;
        float pa = (px2[c] - px1[c]) * (py2[c] - py1[c]);
        c3pe[c] = 3.0f * (pa + 1e-6f);    // 3*(pred_area + eps)
        mk[c]   = -1e30f;
    }

    // ---- Phase 1: existence test.  iou_n > 0.6 <=> 8*I_n - 3*Sg_n > 3*(pa+eps).
    // Track max_n(8*I_n - 3*Sg_n); compare against per-cell constant afterwards.
#pragma unroll 5
    for (int n = 0; n < NGT; n++) {
        float4 bx = s_box[n];
        float m3  = s_m3sa[n];
        #pragma unroll
        for (int c = 0; c < CPT; c++) {
            float cw = fminf(bx.z, px2[c]) - fmaxf(bx.x, px1[c]);
            float chh = fminf(bx.w, py2[c]) - fmaxf(bx.y, py1[c]);
            float I  = fmaxf(cw, 0.0f) * fmaxf(chh, 0.0f);
            mk[c] = fmaxf(mk[c], fmaf(I, 8.0f, m3));
        }
    }

    float loss = 0.0f;
    int bidx[CPT] = {0, 0};
    bool msk[CPT];

    // ---- Phase 2a (rare, predicated per-lane): exact argmax + coord/conf loss
    #pragma unroll
    for (int c = 0; c < CPT; c++) {
        msk[c] = (mk[c] > c3pe[c]);
        if (msk[c]) {
            float paeps = c3pe[c] * (1.0f / 3.0f);
            float bI = -1.0f, bS = 1.0f;
            int bi = 0;
            for (int n = 0; n < NGT; n++) {
                float4 bx = s_box[n];
                float cw = fminf(bx.z, px2[c]) - fmaxf(bx.x, px1[c]);
                float chh = fminf(bx.w, py2[c]) - fmaxf(bx.y, py1[c]);
                float I  = fmaxf(cw, 0.0f) * fmaxf(chh, 0.0f);
                float S  = s_m3sa[n] * (-1.0f / 3.0f) + paeps;
                if (I * bS > bI * S) { bI = I; bS = S; bi = n; }
            }
            bidx[c] = bi;

            const float* bc = base + BLK * c;   // reload raw logits (L2-hot)
            float4 g = s_gt[bi];
            float d0 = bc[0]      - g.x;
            float d1 = bc[HW]     - g.y;
            float d2 = bc[2 * HW] - g.z;
            float d3 = bc[3 * HW] - g.w;
            float dc = 5.0f * conf[c] - 5.0f;
            loss += d0 * d0 + d1 * d1 + d2 * d2 + d3 * d3 + dc * dc;
        } else {
            loss += conf[c] * conf[c];
        }
    }

    // ---- Phase 2b: warp-cooperative class NLL for each masked (lane, c).
    // All lanes of the warp load the 80 class logits in parallel (<=3 each).
    const int W0 = (blockIdx.x * (BLK * CPT) + (wid << 5)) & (HW - 1);
    const float* clbase = outp + ((size_t)ba * CH + 5) * HW;
    #pragma unroll
    for (int c = 0; c < CPT; c++) {
        unsigned bal = __ballot_sync(FULL, msk[c]);
        while (bal) {
            int src = __ffs(bal) - 1;
            bal &= bal - 1;
            int bsrc = __shfl_sync(FULL, bidx[c], src);
            const float* cl = clbase + (W0 + src + BLK * c);
            float s = __expf(cl[(size_t)lane * HW])
                    + __expf(cl[(size_t)(lane + 32) * HW]);
            if (lane < 16) s += __expf(cl[(size_t)(lane + 64) * HW]);
            #pragma unroll
            for (int off = 16; off; off >>= 1)
                s += __shfl_down_sync(FULL, s, off);
            float tot = __shfl_sync(FULL, s, 0);
            if (lane == src) {
                int idx = (int)s_cls[bsrc];
                loss += __logf(tot) - cl[(size_t)idx * HW];
            }
        }
    }

    // block reduction in double
    double v = (double)loss;
    #pragma unroll
    for (int off = 16; off; off >>= 1)
        v += __shfl_down_sync(FULL, v, off);

    if (lane == 0) s_red[wid] = v;
    __syncthreads();
    if (tid < 32) {
        v = (lane < 8) ? s_red[lane] : 0.0;
        #pragma unroll
        for (int off = 4; off; off >>= 1)
            v += __shfl_down_sync(0xffu, v, off);
    }

    // last-block-reduces (single launch, graph-replay safe)
    if (tid == 0) {
        g_part[blockIdx.x] = v;
        __threadfence();
        unsigned int done = atomicAdd(&g_flag, 1u);
        s_last = (done == NBLOCKS - 1);
    }
    __syncthreads();

    if (s_last) {
        double t = 0.0;
        for (int i = tid; i < NBLOCKS; i += BLK)
            t += g_part[i];
        #pragma unroll
        for (int off = 16; off; off >>= 1)
            t += __shfl_down_sync(FULL, t, off);
        if (lane == 0) s_red[wid] = t;
        __syncthreads();
        if (tid == 0) {
            double tot = 0.0;
            #pragma unroll
            for (int i = 0; i < 8; i++) tot += s_red[i];
            out[0] = (float)tot;
            atomicExch(&g_flag, 0u);
        }
    }
}

extern "C" void kernel_launch(void* const* d_in, const int* in_sizes, int n_in,
                              void* d_out, int out_size)
{
    const float* outp    = (const float*)d_in[0];
    const float* target  = (const float*)d_in[1];
    const float* anchors = (const float*)d_in[2];
    float* out = (float*)d_out;

    rl_loss_kernel<<<NBLOCKS, BLK>>>(outp, target, anchors, out);
}